// round 3
// baseline (speedup 1.0000x reference)
#include <cuda_runtime.h>
#include <math.h>

#define Bq 2
#define Nn 4096
#define Mm 12288
#define Kk 64
#define SHh 32
#define Hh 64
#define GKk 8
#define NCc 200

// ---------------- scratch (static device globals; no allocation) ----------------
__device__ float g_losx[Bq*Nn], g_losy[Bq*Nn], g_losz[Bq*Nn];
__device__ float g_pixx[Mm], g_pixy[Mm], g_pixz[Mm], g_pixsq[Mm];
__device__ int   g_nbr[Mm*GKk];
__device__ float g_h0[Bq*Mm*Hh];
__device__ float g_h1[Bq*Mm*Hh];
__device__ float g_part[Bq*96*Hh];

// ---------------- K0: precompute unit vectors ----------------
__global__ void k_pre(const float* __restrict__ xxx, const float* __restrict__ ptp) {
    int i = blockIdx.x * blockDim.x + threadIdx.x;
    if (i < Bq * Nn) {
        int b = i / Nn, n = i - b * Nn;
        float th = xxx[b * 3 * Nn + n];
        float ph = xxx[b * 3 * Nn + Nn + n];
        float st, ct, sp, cp;
        sincosf(th, &st, &ct);
        sincosf(ph, &sp, &cp);
        g_losx[i] = st * cp; g_losy[i] = st * sp; g_losz[i] = ct;
    }
    if (i < Mm) {
        float th = ptp[2 * i], ph = ptp[2 * i + 1];
        float st, ct, sp, cp;
        sincosf(th, &st, &ct);
        sincosf(ph, &sp, &cp);
        float x = st * cp, y = st * sp, z = ct;
        g_pixx[i] = x; g_pixy[i] = y; g_pixz[i] = z;
        g_pixsq[i] = x * x + y * y + z * z;
    }
}

// ---------------- K1: kNN graph (top-8 by dot, self excluded) ----------------
struct Top8 { float v[8]; int id[8]; float vmin; };

__device__ __forceinline__ void t8_init(Top8& t) {
#pragma unroll
    for (int i = 0; i < 8; i++) { t.v[i] = -1e30f; t.id[i] = -1; }
    t.vmin = -1e30f;
}

__device__ __forceinline__ void t8_push(Top8& t, float s, int j) {
    if (s > t.vmin) {
        bool done = false;
#pragma unroll
        for (int i = 0; i < 8; i++) {
            if (!done && t.v[i] == t.vmin) { t.v[i] = s; t.id[i] = j; done = true; }
        }
        float m = t.v[0];
#pragma unroll
        for (int i = 1; i < 8; i++) m = fminf(m, t.v[i]);
        t.vmin = m;
    }
}

__device__ __forceinline__ void t8_merge(Top8& t, int lane, int* __restrict__ out) {
    for (int r = 0; r < 8; r++) {
        float lv = t.v[0]; int ls = 0;
#pragma unroll
        for (int i = 1; i < 8; i++) { if (t.v[i] > lv) { lv = t.v[i]; ls = i; } }
        float bv = lv; int bl = lane;
        for (int off = 16; off; off >>= 1) {
            float ov = __shfl_down_sync(0xffffffffu, bv, off);
            int   ol = __shfl_down_sync(0xffffffffu, bl, off);
            if (ov > bv) { bv = ov; bl = ol; }
        }
        bl = __shfl_sync(0xffffffffu, bl, 0);
        int wj = -1;
        if (lane == bl) {
#pragma unroll
            for (int i = 0; i < 8; i++) {
                if (i == ls) { wj = t.id[i]; t.v[i] = -1e30f; }
            }
        }
        wj = __shfl_sync(0xffffffffu, wj, bl);
        if (lane == 0) out[r] = wj;
    }
}

__global__ void k_knn() {
    __shared__ float sx[1024], sy[1024], sz[1024], sq[1024];
    int tid = threadIdx.x, lane = tid & 31, w = tid >> 5;
    int i0 = blockIdx.x * 16 + w * 2;
    int i1 = i0 + 1;
    float p0x = g_pixx[i0], p0y = g_pixy[i0], p0z = g_pixz[i0];
    float p1x = g_pixx[i1], p1y = g_pixy[i1], p1z = g_pixz[i1];
    Top8 t0, t1; t8_init(t0); t8_init(t1);
    for (int c0 = 0; c0 < Mm; c0 += 1024) {
        for (int t = tid; t < 1024; t += 256) {
            sx[t] = g_pixx[c0 + t]; sy[t] = g_pixy[c0 + t];
            sz[t] = g_pixz[c0 + t]; sq[t] = g_pixsq[c0 + t];
        }
        __syncthreads();
        for (int l = lane; l < 1024; l += 32) {
            int j = c0 + l;
            float cx = sx[l], cy = sy[l], cz = sz[l], cq = sq[l];
            float s0 = 2.f * (p0x * cx + p0y * cy + p0z * cz) - cq;
            float s1 = 2.f * (p1x * cx + p1y * cy + p1z * cz) - cq;
            if (j == i0) s0 = -1e30f;
            if (j == i1) s1 = -1e30f;
            t8_push(t0, s0, j);
            t8_push(t1, s1, j);
        }
        __syncthreads();
    }
    t8_merge(t0, lane, &g_nbr[i0 * 8]);
    t8_merge(t1, lane, &g_nbr[i1 * 8]);
}

// ---------------- K2: sparse sampler (top-64 + attention pool + proj) ----------------
__device__ __forceinline__ unsigned fkey(float f) {
    unsigned u = __float_as_uint(f);
    return (u & 0x80000000u) ? ~u : (u | 0x80000000u);
}

__global__ void k_samp(const float* __restrict__ xxx,
                       const float* __restrict__ aw1, const float* __restrict__ ab1,
                       const float* __restrict__ aw2, const float* __restrict__ ab2,
                       const float* __restrict__ pw,  const float* __restrict__ pb) {
    __shared__ float scos[4096];
    __shared__ unsigned hist[256];
    __shared__ float sval[Kk];
    __shared__ int   sidx[Kk];
    __shared__ float sxg[Kk], slog[Kk];
    __shared__ unsigned s_prefix;
    __shared__ int s_k, s_cnt, s_cnteq;
    __shared__ float s_pooled;
    __shared__ float sw1x[32], sw1d[32], sb1[32], sw2[32];

    int tid = threadIdx.x;
    int bm = blockIdx.x;
    int b = bm / Mm;
    int m = bm - b * Mm;

    float px = g_pixx[m], py = g_pixy[m], pz = g_pixz[m];
    const float* lx = &g_losx[b * Nn];
    const float* ly = &g_losy[b * Nn];
    const float* lz = &g_losz[b * Nn];

    for (int n = tid; n < Nn; n += 256) {
        float d = lx[n] * px + ly[n] * py + lz[n] * pz;
        scos[n] = fminf(1.f, fmaxf(-1.f, d));
    }
    if (tid == 0) { s_prefix = 0u; s_k = Kk; s_cnt = 0; s_cnteq = 0; }
    if (tid < 32) {
        sw1x[tid] = aw1[tid];
        sw1d[tid] = aw1[32 + tid];
        sb1[tid]  = ab1[tid];
        sw2[tid]  = aw2[tid];
    }
    __syncthreads();

    // 4-pass radix select: exact key of the 64th-largest value
#pragma unroll
    for (int pass = 0; pass < 4; pass++) {
        int shift = 24 - 8 * pass;
        unsigned pmask = (pass == 0) ? 0u : (0xFFFFFFFFu << (shift + 8));
        hist[tid] = 0u;
        __syncthreads();
        unsigned pref = s_prefix;
        int kk = s_k;
        for (int n = tid; n < Nn; n += 256) {
            unsigned key = fkey(scos[n]);
            if ((key & pmask) == pref) atomicAdd(&hist[(key >> shift) & 255], 1u);
        }
        __syncthreads();
        // in-place suffix sum over 256 bins
        for (int off = 1; off < 256; off <<= 1) {
            unsigned v = (tid + off < 256) ? hist[tid + off] : 0u;
            __syncthreads();
            hist[tid] += v;
            __syncthreads();
        }
        unsigned sfx  = hist[tid];
        unsigned sfx1 = (tid < 255) ? hist[tid + 1] : 0u;
        if (sfx >= (unsigned)kk && sfx1 < (unsigned)kk) {
            s_prefix = pref | ((unsigned)tid << shift);
            s_k = kk - (int)sfx1;
        }
        __syncthreads();
    }

    unsigned T = s_prefix;
    int needEq = s_k;
    int base = Kk - needEq;
    for (int n = tid; n < Nn; n += 256) {
        float v = scos[n];
        unsigned key = fkey(v);
        if (key > T) {
            int p = atomicAdd(&s_cnt, 1);
            sval[p] = v; sidx[p] = n;
        }
    }
    __syncthreads();
    for (int n = tid; n < Nn; n += 256) {
        float v = scos[n];
        unsigned key = fkey(v);
        if (key == T) {
            int p = atomicAdd(&s_cnteq, 1);
            if (p < needEq) { sval[base + p] = v; sidx[base + p] = n; }
        }
    }
    __syncthreads();

    // attention MLP per selected element
    if (tid < Kk) {
        float v = sval[tid];
        int id = sidx[tid];
        float xg = xxx[b * 3 * Nn + 2 * Nn + id];
        float d = acosf(fminf(1.f, fmaxf(-1.f, v)));
        float acc = ab2[0];
#pragma unroll
        for (int s = 0; s < 32; s++) {
            float hh = fmaf(xg, sw1x[s], fmaf(d, sw1d[s], sb1[s]));
            acc = fmaf(fmaxf(hh, 0.f), sw2[s], acc);
        }
        slog[tid] = acc;
        sxg[tid] = xg;
    }
    __syncthreads();

    // softmax + weighted pool (warp 0, shuffle reductions)
    if (tid < 32) {
        float a  = slog[tid], bb = slog[tid + 32];
        float mx = fmaxf(a, bb);
#pragma unroll
        for (int off = 16; off; off >>= 1) mx = fmaxf(mx, __shfl_xor_sync(0xffffffffu, mx, off));
        float e1 = __expf(a - mx), e2 = __expf(bb - mx);
        float sm = e1 + e2;
        float wx = e1 * sxg[tid] + e2 * sxg[tid + 32];
#pragma unroll
        for (int off = 16; off; off >>= 1) {
            sm += __shfl_xor_sync(0xffffffffu, sm, off);
            wx += __shfl_xor_sync(0xffffffffu, wx, off);
        }
        if (tid == 0) s_pooled = wx / sm;
    }
    __syncthreads();
    if (tid < Hh) {
        float p = s_pooled;
        g_h0[bm * Hh + tid] = fmaxf(fmaf(p, pw[tid], pb[tid]), 0.f);
    }
}

// ---------------- K3: one GNN layer (agg@rel_w + h@root_w + bias, relu) ----------------
__global__ void k_gnn(const float* __restrict__ relw, const float* __restrict__ relb,
                      const float* __restrict__ rootw, int layer, int dir) {
    extern __shared__ float smbuf[];
    float* swr   = smbuf;            // 4096
    float* swo   = smbuf + 4096;     // 4096
    float* sagg  = smbuf + 8192;     // 4096
    float* shin  = smbuf + 12288;    // 4096
    float* sbias = smbuf + 16384;    // 64
    int*   snbr  = (int*)(smbuf + 16448); // 512 ints

    const float* hin  = dir ? g_h1 : g_h0;
    float*       hout = dir ? g_h0 : g_h1;

    int tid = threadIdx.x;
    int row0 = blockIdx.x * 64;
    int b = row0 / Mm;
    int m0 = row0 - b * Mm;

    for (int i = tid; i < 4096; i += 256) {
        swr[i]  = relw[layer * 4096 + i];
        swo[i]  = rootw[layer * 4096 + i];
        shin[i] = hin[row0 * 64 + i];
    }
    if (tid < 64) sbias[tid] = relb[layer * 64 + tid];
    for (int i = tid; i < 512; i += 256) snbr[i] = g_nbr[m0 * 8 + i];
    __syncthreads();

    int c = tid & 63;
    int rq = tid >> 6;

    // neighbor-sum aggregation
    for (int rr = rq; rr < 64; rr += 4) {
        float a = 0.f;
#pragma unroll
        for (int j = 0; j < 8; j++) {
            int nb = snbr[rr * 8 + j];
            a += hin[(b * Mm + nb) * 64 + c];
        }
        sagg[rr * 64 + c] = a;
    }
    __syncthreads();

    float acc[16];
#pragma unroll
    for (int i = 0; i < 16; i++) acc[i] = sbias[c];
    int rbase = rq * 16;
    for (int k = 0; k < 64; k++) {
        float wr = swr[k * 64 + c];
        float wo = swo[k * 64 + c];
#pragma unroll
        for (int i = 0; i < 16; i++) {
            acc[i] += sagg[(rbase + i) * 64 + k] * wr + shin[(rbase + i) * 64 + k] * wo;
        }
    }
#pragma unroll
    for (int i = 0; i < 16; i++)
        hout[(row0 + rbase + i) * 64 + c] = fmaxf(acc[i], 0.f);
}

// ---------------- K4a: partial mean-pool reduction ----------------
__global__ void k_red() {
    __shared__ float part[128];
    int tid = threadIdx.x;
    int blk = blockIdx.x;
    int b = blk / 96, seg = blk % 96;
    int c = tid & 63, half = tid >> 6;
    float a = 0.f;
    int mbase = seg * 128;
    for (int i = half; i < 128; i += 2)
        a += g_h1[(b * Mm + mbase + i) * 64 + c];
    part[tid] = a;
    __syncthreads();
    if (tid < 64) g_part[(b * 96 + seg) * 64 + c] = part[tid] + part[tid + 64];
}

// ---------------- K4b: final reduce + output MLP ----------------
__global__ void k_out(const float* __restrict__ ow1, const float* __restrict__ ob1,
                      const float* __restrict__ ow2, const float* __restrict__ ob2,
                      float* __restrict__ out) {
    __shared__ float sgf[64], shid[64];
    int tid = threadIdx.x;
    int b = blockIdx.x;
    if (tid < 64) {
        float a = 0.f;
        for (int s = 0; s < 96; s++) a += g_part[(b * 96 + s) * 64 + tid];
        sgf[tid] = a * (1.f / (float)Mm);
    }
    __syncthreads();
    if (tid < 64) {
        float a = ob1[tid];
        for (int k = 0; k < 64; k++) a = fmaf(sgf[k], ow1[k * 64 + tid], a);
        shid[tid] = fmaxf(a, 0.f);
    }
    __syncthreads();
    if (tid < NCc) {
        float a = ob2[tid];
        for (int k = 0; k < 64; k++) a = fmaf(shid[k], ow2[k * NCc + tid], a);
        out[b * NCc + tid] = a;
    }
}

// ---------------- launch ----------------
extern "C" void kernel_launch(void* const* d_in, const int* in_sizes, int n_in,
                              void* d_out, int out_size) {
    const float* xxx  = (const float*)d_in[0];
    const float* ptp  = (const float*)d_in[1];
    const float* aw1  = (const float*)d_in[2];
    const float* ab1  = (const float*)d_in[3];
    const float* aw2  = (const float*)d_in[4];
    const float* ab2  = (const float*)d_in[5];
    const float* pw   = (const float*)d_in[6];
    const float* pb   = (const float*)d_in[7];
    const float* relw = (const float*)d_in[8];
    const float* relb = (const float*)d_in[9];
    const float* rootw= (const float*)d_in[10];
    const float* ow1  = (const float*)d_in[11];
    const float* ob1  = (const float*)d_in[12];
    const float* ow2  = (const float*)d_in[13];
    const float* ob2  = (const float*)d_in[14];
    float* out = (float*)d_out;

    (void)in_sizes; (void)n_in; (void)out_size;

    k_pre<<<48, 256>>>(xxx, ptp);
    k_knn<<<Mm / 16, 256>>>();
    k_samp<<<Bq * Mm, 256>>>(xxx, aw1, ab1, aw2, ab2, pw, pb);

    const int SM3 = 16960 * 4; // 67840 bytes dynamic shared
    cudaFuncSetAttribute(k_gnn, cudaFuncAttributeMaxDynamicSharedMemorySize, SM3);
    k_gnn<<<384, 256, SM3>>>(relw, relb, rootw, 0, 0); // g_h0 -> g_h1
    k_gnn<<<384, 256, SM3>>>(relw, relb, rootw, 1, 1); // g_h1 -> g_h0
    k_gnn<<<384, 256, SM3>>>(relw, relb, rootw, 2, 0); // g_h0 -> g_h1

    k_red<<<Bq * 96, 128>>>();
    k_out<<<Bq, 256>>>(ow1, ob1, ow2, ob2, out);
}

// round 4
// speedup vs baseline: 1.1702x; 1.1702x over previous
#include <cuda_runtime.h>
#include <math.h>

#define Bq 2
#define Nn 4096
#define Mm 12288
#define Kk 64
#define SHh 32
#define Hh 64
#define GKk 8
#define NCc 200

// ---------------- scratch (static device globals; no allocation) ----------------
__device__ float4 g_los4[Bq*Nn];   // x,y,z,feat
__device__ float4 g_pix4[Mm];      // x,y,z,|p|^2
__device__ int    g_nbr[Mm*GKk];
__device__ float  g_h0[Bq*Mm*Hh];
__device__ float  g_h1[Bq*Mm*Hh];
__device__ float  g_part[Bq*96*Hh];

// ---------------- K0: precompute packed unit vectors ----------------
__global__ void k_pre(const float* __restrict__ xxx, const float* __restrict__ ptp) {
    int i = blockIdx.x * blockDim.x + threadIdx.x;
    if (i < Bq * Nn) {
        int b = i / Nn, n = i - b * Nn;
        float th = xxx[b * 3 * Nn + n];
        float ph = xxx[b * 3 * Nn + Nn + n];
        float ft = xxx[b * 3 * Nn + 2 * Nn + n];
        float st, ct, sp, cp;
        sincosf(th, &st, &ct);
        sincosf(ph, &sp, &cp);
        g_los4[i] = make_float4(st * cp, st * sp, ct, ft);
    }
    if (i < Mm) {
        float th = ptp[2 * i], ph = ptp[2 * i + 1];
        float st, ct, sp, cp;
        sincosf(th, &st, &ct);
        sincosf(ph, &sp, &cp);
        float x = st * cp, y = st * sp, z = ct;
        g_pix4[i] = make_float4(x, y, z, x * x + y * y + z * z);
    }
}

// ---------------- K1: kNN graph (top-8 by dot, self excluded) ----------------
struct Top8 { float v[8]; int id[8]; float vmin; };

__device__ __forceinline__ void t8_init(Top8& t) {
#pragma unroll
    for (int i = 0; i < 8; i++) { t.v[i] = -1e30f; t.id[i] = -1; }
    t.vmin = -1e30f;
}

__device__ __forceinline__ void t8_push(Top8& t, float s, int j) {
    if (s > t.vmin) {
        bool done = false;
#pragma unroll
        for (int i = 0; i < 8; i++) {
            if (!done && t.v[i] == t.vmin) { t.v[i] = s; t.id[i] = j; done = true; }
        }
        float m = t.v[0];
#pragma unroll
        for (int i = 1; i < 8; i++) m = fminf(m, t.v[i]);
        t.vmin = m;
    }
}

__device__ __forceinline__ void t8_merge(Top8& t, int lane, int* __restrict__ out) {
    for (int r = 0; r < 8; r++) {
        float lv = t.v[0]; int ls = 0;
#pragma unroll
        for (int i = 1; i < 8; i++) { if (t.v[i] > lv) { lv = t.v[i]; ls = i; } }
        float bv = lv; int bl = lane;
        for (int off = 16; off; off >>= 1) {
            float ov = __shfl_down_sync(0xffffffffu, bv, off);
            int   ol = __shfl_down_sync(0xffffffffu, bl, off);
            if (ov > bv) { bv = ov; bl = ol; }
        }
        bl = __shfl_sync(0xffffffffu, bl, 0);
        int wj = -1;
        if (lane == bl) {
#pragma unroll
            for (int i = 0; i < 8; i++) {
                if (i == ls) { wj = t.id[i]; t.v[i] = -1e30f; }
            }
        }
        wj = __shfl_sync(0xffffffffu, wj, bl);
        if (lane == 0) out[r] = wj;
    }
}

__global__ void k_knn() {
    __shared__ float4 sp[1024];
    int tid = threadIdx.x, lane = tid & 31, w = tid >> 5;
    int i0 = blockIdx.x * 16 + w * 2;
    int i1 = i0 + 1;
    float4 p0 = g_pix4[i0];
    float4 p1 = g_pix4[i1];
    Top8 t0, t1; t8_init(t0); t8_init(t1);
    for (int c0 = 0; c0 < Mm; c0 += 1024) {
        for (int t = tid; t < 1024; t += 256) sp[t] = g_pix4[c0 + t];
        __syncthreads();
        for (int l = lane; l < 1024; l += 32) {
            int j = c0 + l;
            float4 c = sp[l];
            float s0 = 2.f * (p0.x * c.x + p0.y * c.y + p0.z * c.z) - c.w;
            float s1 = 2.f * (p1.x * c.x + p1.y * c.y + p1.z * c.z) - c.w;
            if (j == i0) s0 = -1e30f;
            if (j == i1) s1 = -1e30f;
            t8_push(t0, s0, j);
            t8_push(t1, s1, j);
        }
        __syncthreads();
    }
    t8_merge(t0, lane, &g_nbr[i0 * 8]);
    t8_merge(t1, lane, &g_nbr[i1 * 8]);
}

// ---------------- K2: sparse sampler (linear-hist top-64 + attn pool + proj) ----------------
__global__ void k_samp(const float* __restrict__ aw1, const float* __restrict__ ab1,
                       const float* __restrict__ aw2, const float* __restrict__ ab2,
                       const float* __restrict__ pw,  const float* __restrict__ pb) {
    __shared__ float scos[4096];
    __shared__ unsigned hist[2048];
    __shared__ unsigned csfx[257];
    __shared__ float sval[Kk];
    __shared__ int   sidx[Kk];
    __shared__ float cv[256];
    __shared__ int   cidx[256];
    __shared__ float sxg[Kk], slog[Kk];
    __shared__ int s_tb, s_cntgt, s_cnt, s_ceq;
    __shared__ float s_pooled;
    __shared__ float sw1x[32], sw1d[32], sb1[32], sw2[32];

    int tid = threadIdx.x;
    int bm = blockIdx.x;
    int b = bm / Mm;
    int m = bm - b * Mm;

    float4 p = g_pix4[m];
    const float4* los = &g_los4[b * Nn];

    // init
#pragma unroll
    for (int i = 0; i < 8; i++) hist[tid + 256 * i] = 0u;
    if (tid == 0) { s_cnt = 0; s_ceq = 0; csfx[256] = 0u; }
    if (tid < 32) {
        sw1x[tid] = aw1[tid];
        sw1d[tid] = aw1[32 + tid];
        sb1[tid]  = ab1[tid];
        sw2[tid]  = aw2[tid];
    }
    __syncthreads();

    // pass 1: dots + linear histogram (2048 bins over [-1,1])
    for (int n = tid; n < Nn; n += 256) {
        float4 l = los[n];
        float d = l.x * p.x + l.y * p.y + l.z * p.z;
        float v = fminf(1.f, fmaxf(-1.f, d));
        scos[n] = v;
        int bin = min(2047, (int)((v + 1.f) * 1024.f));
        atomicAdd(&hist[bin], 1u);
    }
    __syncthreads();

    // coarse suffix scan over 256 groups of 8 bins
    {
        unsigned c = 0;
#pragma unroll
        for (int j = 0; j < 8; j++) c += hist[tid * 8 + j];
        csfx[tid] = c;
    }
    __syncthreads();
    for (int off = 1; off < 256; off <<= 1) {
        unsigned v = (tid + off < 256) ? csfx[tid + off] : 0u;
        __syncthreads();
        csfx[tid] += v;
        __syncthreads();
    }
    {
        unsigned sfx = csfx[tid];
        unsigned nxt = csfx[tid + 1];
        if (sfx >= (unsigned)Kk && nxt < (unsigned)Kk) {
            unsigned run = nxt;
            for (int bin = tid * 8 + 7; bin >= tid * 8; --bin) {
                run += hist[bin];
                if (run >= (unsigned)Kk) {
                    s_tb = bin;
                    s_cntgt = (int)(run - hist[bin]);
                    break;
                }
            }
        }
    }
    __syncthreads();

    // pass 2: collect values above threshold bin; gather threshold-bin candidates
    int tb = s_tb;
    for (int n = tid; n < Nn; n += 256) {
        float v = scos[n];
        int bin = min(2047, (int)((v + 1.f) * 1024.f));
        if (bin > tb) {
            int pp = atomicAdd(&s_cnt, 1);
            sval[pp] = v; sidx[pp] = n;
        } else if (bin == tb) {
            int pp = atomicAdd(&s_ceq, 1);
            if (pp < 256) { cv[pp] = v; cidx[pp] = n; }
        }
    }
    __syncthreads();

    // exact rank selection inside threshold bin (tiny candidate set)
    int needEq = Kk - s_cntgt;
    int cc = min(s_ceq, 256);
    for (int t = tid; t < cc; t += 256) {
        float v = cv[t]; int id = cidx[t];
        int rank = 0;
        for (int j = 0; j < cc; j++) {
            float vj = cv[j];
            rank += (vj > v) || (vj == v && cidx[j] < id);
        }
        if (rank < needEq) {
            int pp = atomicAdd(&s_cnt, 1);
            sval[pp] = v; sidx[pp] = id;
        }
    }
    __syncthreads();

    // attention MLP per selected element
    if (tid < Kk) {
        float v = sval[tid];
        int id = sidx[tid];
        float xg = los[id].w;
        float d = acosf(fminf(1.f, fmaxf(-1.f, v)));
        float acc = ab2[0];
#pragma unroll
        for (int s = 0; s < 32; s++) {
            float hh = fmaf(xg, sw1x[s], fmaf(d, sw1d[s], sb1[s]));
            acc = fmaf(fmaxf(hh, 0.f), sw2[s], acc);
        }
        slog[tid] = acc;
        sxg[tid] = xg;
    }
    __syncthreads();

    // softmax + weighted pool (warp 0)
    if (tid < 32) {
        float a  = slog[tid], bb = slog[tid + 32];
        float mx = fmaxf(a, bb);
#pragma unroll
        for (int off = 16; off; off >>= 1) mx = fmaxf(mx, __shfl_xor_sync(0xffffffffu, mx, off));
        float e1 = __expf(a - mx), e2 = __expf(bb - mx);
        float sm = e1 + e2;
        float wx = e1 * sxg[tid] + e2 * sxg[tid + 32];
#pragma unroll
        for (int off = 16; off; off >>= 1) {
            sm += __shfl_xor_sync(0xffffffffu, sm, off);
            wx += __shfl_xor_sync(0xffffffffu, wx, off);
        }
        if (tid == 0) s_pooled = wx / sm;
    }
    __syncthreads();
    if (tid < Hh) {
        float pp = s_pooled;
        g_h0[bm * Hh + tid] = fmaxf(fmaf(pp, pw[tid], pb[tid]), 0.f);
    }
}

// ---------------- K3: GNN layer, fused [agg|h] @ [[rel];[root]], 4x4 reg tiling ----------------
// shared layout (floats): sAT[128][65] @0, sW[128][64] @8320, sbias[64] @16512, snbr(int)[512] @16576
#define GNN_SMEMF 17088
__global__ void k_gnn(const float* __restrict__ relw, const float* __restrict__ relb,
                      const float* __restrict__ rootw, int layer, int dir) {
    extern __shared__ float smbuf[];
    float* sAT   = smbuf;                 // [k][r], padded stride 65
    float* sW    = smbuf + 8320;          // [k][c], stride 64
    float* sbias = smbuf + 16512;
    int*   snbr  = (int*)(smbuf + 16576);

    const float* hin  = dir ? g_h1 : g_h0;
    float*       hout = dir ? g_h0 : g_h1;

    int tid = threadIdx.x;
    int row0 = blockIdx.x * 64;
    int b = row0 / Mm;
    int m0 = row0 - b * Mm;

    // weights: sW[k][c], k<64 -> rel, k>=64 -> root
    for (int i = tid; i < 4096; i += 256) {
        sW[i]        = relw[layer * 4096 + i];
        sW[4096 + i] = rootw[layer * 4096 + i];
    }
    if (tid < 64) sbias[tid] = relb[layer * 64 + tid];
    for (int i = tid; i < 512; i += 256) snbr[i] = g_nbr[m0 * 8 + i];
    // h tile -> transposed (conflict-free via pad-65): sAT[64+k][r]
    for (int i = tid; i < 4096; i += 256) {
        int r = i >> 6, k = i & 63;
        sAT[(64 + k) * 65 + r] = hin[row0 * 64 + i];
    }
    __syncthreads();

    // neighbor-sum aggregation -> sAT[k][r] for k<64 (k = feature = c here)
    {
        int c = tid & 63;
        int rq = tid >> 6;
        for (int rr = rq; rr < 64; rr += 4) {
            float a = 0.f;
#pragma unroll
            for (int j = 0; j < 8; j++) {
                int nb = snbr[rr * 8 + j];
                a += hin[(b * Mm + nb) * 64 + c];
            }
            sAT[c * 65 + rr] = a;
        }
    }
    __syncthreads();

    // GEMM: C[64][64] = A[64][128] @ W[128][64], 4x4 per thread
    int tx = tid & 15, ty = tid >> 4;
    int r0 = ty * 4, c0 = tx * 4;
    float acc[4][4];
#pragma unroll
    for (int i = 0; i < 4; i++)
#pragma unroll
        for (int j = 0; j < 4; j++) acc[i][j] = sbias[c0 + j];

#pragma unroll 4
    for (int k = 0; k < 128; k++) {
        float a0 = sAT[k * 65 + r0];
        float a1 = sAT[k * 65 + r0 + 1];
        float a2 = sAT[k * 65 + r0 + 2];
        float a3 = sAT[k * 65 + r0 + 3];
        float4 wv = *(const float4*)&sW[k * 64 + c0];
        acc[0][0] = fmaf(a0, wv.x, acc[0][0]); acc[0][1] = fmaf(a0, wv.y, acc[0][1]);
        acc[0][2] = fmaf(a0, wv.z, acc[0][2]); acc[0][3] = fmaf(a0, wv.w, acc[0][3]);
        acc[1][0] = fmaf(a1, wv.x, acc[1][0]); acc[1][1] = fmaf(a1, wv.y, acc[1][1]);
        acc[1][2] = fmaf(a1, wv.z, acc[1][2]); acc[1][3] = fmaf(a1, wv.w, acc[1][3]);
        acc[2][0] = fmaf(a2, wv.x, acc[2][0]); acc[2][1] = fmaf(a2, wv.y, acc[2][1]);
        acc[2][2] = fmaf(a2, wv.z, acc[2][2]); acc[2][3] = fmaf(a2, wv.w, acc[2][3]);
        acc[3][0] = fmaf(a3, wv.x, acc[3][0]); acc[3][1] = fmaf(a3, wv.y, acc[3][1]);
        acc[3][2] = fmaf(a3, wv.z, acc[3][2]); acc[3][3] = fmaf(a3, wv.w, acc[3][3]);
    }
#pragma unroll
    for (int i = 0; i < 4; i++) {
        float4 o;
        o.x = fmaxf(acc[i][0], 0.f);
        o.y = fmaxf(acc[i][1], 0.f);
        o.z = fmaxf(acc[i][2], 0.f);
        o.w = fmaxf(acc[i][3], 0.f);
        *(float4*)&hout[(row0 + r0 + i) * 64 + c0] = o;
    }
}

// ---------------- K4a: partial mean-pool reduction ----------------
__global__ void k_red() {
    __shared__ float part[128];
    int tid = threadIdx.x;
    int blk = blockIdx.x;
    int b = blk / 96, seg = blk % 96;
    int c = tid & 63, half = tid >> 6;
    float a = 0.f;
    int mbase = seg * 128;
    for (int i = half; i < 128; i += 2)
        a += g_h1[(b * Mm + mbase + i) * 64 + c];
    part[tid] = a;
    __syncthreads();
    if (tid < 64) g_part[(b * 96 + seg) * 64 + c] = part[tid] + part[tid + 64];
}

// ---------------- K4b: final reduce + output MLP ----------------
__global__ void k_out(const float* __restrict__ ow1, const float* __restrict__ ob1,
                      const float* __restrict__ ow2, const float* __restrict__ ob2,
                      float* __restrict__ out) {
    __shared__ float sgf[64], shid[64];
    int tid = threadIdx.x;
    int b = blockIdx.x;
    if (tid < 64) {
        float a = 0.f;
        for (int s = 0; s < 96; s++) a += g_part[(b * 96 + s) * 64 + tid];
        sgf[tid] = a * (1.f / (float)Mm);
    }
    __syncthreads();
    if (tid < 64) {
        float a = ob1[tid];
        for (int k = 0; k < 64; k++) a = fmaf(sgf[k], ow1[k * 64 + tid], a);
        shid[tid] = fmaxf(a, 0.f);
    }
    __syncthreads();
    if (tid < NCc) {
        float a = ob2[tid];
        for (int k = 0; k < 64; k++) a = fmaf(shid[k], ow2[k * NCc + tid], a);
        out[b * NCc + tid] = a;
    }
}

// ---------------- launch ----------------
extern "C" void kernel_launch(void* const* d_in, const int* in_sizes, int n_in,
                              void* d_out, int out_size) {
    const float* xxx  = (const float*)d_in[0];
    const float* ptp  = (const float*)d_in[1];
    const float* aw1  = (const float*)d_in[2];
    const float* ab1  = (const float*)d_in[3];
    const float* aw2  = (const float*)d_in[4];
    const float* ab2  = (const float*)d_in[5];
    const float* pw   = (const float*)d_in[6];
    const float* pb   = (const float*)d_in[7];
    const float* relw = (const float*)d_in[8];
    const float* relb = (const float*)d_in[9];
    const float* rootw= (const float*)d_in[10];
    const float* ow1  = (const float*)d_in[11];
    const float* ob1  = (const float*)d_in[12];
    const float* ow2  = (const float*)d_in[13];
    const float* ob2  = (const float*)d_in[14];
    float* out = (float*)d_out;

    (void)in_sizes; (void)n_in; (void)out_size;

    k_pre<<<48, 256>>>(xxx, ptp);
    k_knn<<<Mm / 16, 256>>>();
    k_samp<<<Bq * Mm, 256>>>(aw1, ab1, aw2, ab2, pw, pb);

    const int SM3 = GNN_SMEMF * 4;
    cudaFuncSetAttribute(k_gnn, cudaFuncAttributeMaxDynamicSharedMemorySize, SM3);
    k_gnn<<<384, 256, SM3>>>(relw, relb, rootw, 0, 0); // g_h0 -> g_h1
    k_gnn<<<384, 256, SM3>>>(relw, relb, rootw, 1, 1); // g_h1 -> g_h0
    k_gnn<<<384, 256, SM3>>>(relw, relb, rootw, 2, 0); // g_h0 -> g_h1

    k_red<<<Bq * 96, 128>>>();
    k_out<<<Bq, 256>>>(ow1, ob1, ow2, ob2, out);
}